// round 3
// baseline (speedup 1.0000x reference)
#include <cuda_runtime.h>
#include <math.h>

// Problem constants (fixed by the dataset)
#define NMAX   100000
#define EMAX   1000000
#define DIM    64
#define Hdim   14     // H = 2*LAT
#define PD     16     // P = (LAT+1)*R
#define LATC   7
#define OUTC   30     // 7 loc + 7 scale + 14 U + 2 m
#define SP_INV_1 0.5413248546129181f

// ---------------- scratch (static device globals; no allocation allowed) ---
__device__ float4 g_Y1[NMAX * 4];     // X@W1, padded 16 feats (last 2 = 0)
__device__ float4 g_Y2[NMAX * 4];     // relu(agg1)@W2, padded 16 feats
__device__ int    g_cnt[NMAX + 1];    // degree histogram; [NMAX] = scan total
__device__ int    g_start[NMAX];      // bucket base offsets (disjoint)
__device__ int    g_cursor[NMAX];     // fill cursors (== bucket end after fill)
__device__ int2   g_edge[EMAX];       // (col, val_bits) bucketed by row

// ---------------- K_FAT: gemm1 (blocks < gN) || histogram (rest) -----------
__global__ void k_fat(const float* __restrict__ X, const float* __restrict__ W1,
                      const int* __restrict__ rows, int N, int E, int gN) {
    if ((int)blockIdx.x >= gN) {
        // histogram part
        int e = (blockIdx.x - gN) * blockDim.x + threadIdx.x;
        if (e < E) atomicAdd(&g_cnt[rows[e]], 1);
        return;
    }

    // gemm part: Y1 = X @ W1 (N x 64 x 14)
    __shared__ float sW[DIM * Hdim];   // 896 floats
    for (int t = threadIdx.x; t < DIM * Hdim; t += blockDim.x)
        sW[t] = W1[t];
    __syncthreads();

    int i = blockIdx.x * blockDim.x + threadIdx.x;
    if (i >= N) return;

    const float4* x4 = (const float4*)(X + (long)i * DIM);
    float acc[Hdim];
#pragma unroll
    for (int j = 0; j < Hdim; ++j) acc[j] = 0.f;

#pragma unroll
    for (int k4 = 0; k4 < DIM / 4; ++k4) {
        float4 x = x4[k4];
        const float* w = &sW[k4 * 4 * Hdim];
#pragma unroll
        for (int j = 0; j < Hdim; ++j)
            acc[j] += x.x * w[j] + x.y * w[Hdim + j]
                    + x.z * w[2 * Hdim + j] + x.w * w[3 * Hdim + j];
    }

    g_Y1[i * 4 + 0] = make_float4(acc[0], acc[1], acc[2], acc[3]);
    g_Y1[i * 4 + 1] = make_float4(acc[4], acc[5], acc[6], acc[7]);
    g_Y1[i * 4 + 2] = make_float4(acc[8], acc[9], acc[10], acc[11]);
    g_Y1[i * 4 + 3] = make_float4(acc[12], acc[13], 0.f, 0.f);
}

// ---------------- one-pass scan: disjoint bucket bases via atomic total -----
__global__ void k_scan(int N) {
    int t = threadIdx.x;
    int i = blockIdx.x * 256 + t;
    int v = (i < N) ? g_cnt[i] : 0;

    int lane = t & 31, w = t >> 5;
    // warp inclusive scan
    int x = v;
#pragma unroll
    for (int off = 1; off < 32; off <<= 1) {
        int y = __shfl_up_sync(0xffffffffu, x, off);
        if (lane >= off) x += y;
    }

    __shared__ int wsum[8];
    __shared__ int bbase;
    if (lane == 31) wsum[w] = x;
    __syncthreads();
    if (t < 8) {
        int s = wsum[t];
#pragma unroll
        for (int off = 1; off < 8; off <<= 1) {
            int y = __shfl_up_sync(0xffu, s, off);
            if (t >= off) s += y;
        }
        wsum[t] = s;                       // inclusive warp-sum scan
        if (t == 7) bbase = atomicAdd(&g_cnt[NMAX], s);  // block base
    }
    __syncthreads();

    if (i < N) {
        int excl = (x - v) + ((w > 0) ? wsum[w - 1] : 0);
        int st = bbase + excl;
        g_start[i]  = st;
        g_cursor[i] = st;
    }
}

__global__ void k_fill(const int* __restrict__ rows, const int* __restrict__ cols,
                       const float* __restrict__ vals, int E) {
    int e = blockIdx.x * blockDim.x + threadIdx.x;
    if (e >= E) return;
    int r = rows[e];
    int pos = atomicAdd(&g_cursor[r], 1);
    g_edge[pos] = make_int2(cols[e], __float_as_int(vals[e]));
}

// ---------------- helpers ---------------------------------------------------
__device__ __forceinline__ float ftanh(float x) {
    x = fminf(fmaxf(x, -15.f), 15.f);
    float e = __expf(2.f * x);
    return (e - 1.f) / (e + 1.f);
}
__device__ __forceinline__ float fsoftplus(float x) {
    return log1pf(__expf(x));   // input range ~[-0.46, 1.54]: safe
}

// 8 lanes per node: lane team (half = 0/1) splits edges stride-2;
// each lane owns float4 chunk q. Combine halves with shfl_xor(4).
__device__ __forceinline__ float4 csr_agg8(const float4* __restrict__ src,
                                           int i, int q, int half) {
    int start = g_start[i];
    int end   = g_cursor[i];    // == start + cnt after fill
    float4 acc = make_float4(0.f, 0.f, 0.f, 0.f);
    for (int e = start + half; e < end; e += 2) {
        int2 ed = __ldg(&g_edge[e]);
        float v = __int_as_float(ed.y);
        float4 s = __ldg(&src[(long)ed.x * 4 + q]);
        acc.x += v * s.x; acc.y += v * s.y;
        acc.z += v * s.z; acc.w += v * s.w;
    }
    acc.x += __shfl_xor_sync(0xffffffffu, acc.x, 4);
    acc.y += __shfl_xor_sync(0xffffffffu, acc.y, 4);
    acc.z += __shfl_xor_sync(0xffffffffu, acc.z, 4);
    acc.w += __shfl_xor_sync(0xffffffffu, acc.w, 4);
    return acc;
}

// broadcast the 16 h-values of this node's lane-octet into h[16]
__device__ __forceinline__ void group_bcast(float4 acc, float* h, int lane) {
    int base = lane & ~7;
#pragma unroll
    for (int sq = 0; sq < 4; ++sq) {
        h[4 * sq + 0] = __shfl_sync(0xffffffffu, acc.x, base + sq);
        h[4 * sq + 1] = __shfl_sync(0xffffffffu, acc.y, base + sq);
        h[4 * sq + 2] = __shfl_sync(0xffffffffu, acc.z, base + sq);
        h[4 * sq + 3] = __shfl_sync(0xffffffffu, acc.w, base + sq);
    }
}

// ---------------- K_AGG1: Y2 = relu(agg(Y1)) @ W2 (fused) ------------------
__global__ void k_agg1(const float* __restrict__ W2, int N) {
    __shared__ float sW[Hdim * 16];    // W2 padded to 14x16, pads = 0
    for (int t = threadIdx.x; t < Hdim * 16; t += blockDim.x) {
        int k = t >> 4, j = t & 15;
        sW[t] = (j < Hdim) ? W2[k * Hdim + j] : 0.f;
    }
    __syncthreads();

    int tid = blockIdx.x * blockDim.x + threadIdx.x;
    int i = tid >> 3, q = tid & 3, half = (tid >> 2) & 1;
    bool valid = (i < N);
    int ic = valid ? i : 0;

    float4 acc = make_float4(0.f, 0.f, 0.f, 0.f);
    if (valid) acc = csr_agg8(g_Y1, ic, q, half);

    acc.x = fmaxf(acc.x, 0.f); acc.y = fmaxf(acc.y, 0.f);
    acc.z = fmaxf(acc.z, 0.f); acc.w = fmaxf(acc.w, 0.f);

    float h[16];
    group_bcast(acc, h, threadIdx.x & 31);

    int j0 = q * 4;
    float y[4] = {0.f, 0.f, 0.f, 0.f};
#pragma unroll
    for (int k = 0; k < Hdim; ++k) {
        float hk = h[k];
#pragma unroll
        for (int d = 0; d < 4; ++d)
            y[d] += hk * sW[k * 16 + j0 + d];
    }

    if (valid && half == 0)
        g_Y2[(long)i * 4 + q] = make_float4(y[0], y[1], y[2], y[3]);
}

// ---------------- K_AGG2: agg(Y2) -> relu -> heads -> out (fused) ----------
__global__ void k_agg2(const float* __restrict__ Wd1, const float* __restrict__ bd1,
                       const float* __restrict__ Wd2, const float* __restrict__ bd2,
                       float* __restrict__ out, int N) {
    __shared__ float sW1[Hdim * 16];   // Wd1 padded 14x16
    __shared__ float sW2[Hdim * 16];   // Wd2 14x16 (natural)
    __shared__ float sB1[16];
    __shared__ float sB2[16];
    for (int t = threadIdx.x; t < Hdim * 16; t += blockDim.x) {
        int k = t >> 4, j = t & 15;
        sW1[t] = (j < Hdim) ? Wd1[k * Hdim + j] : 0.f;
        sW2[t] = Wd2[k * PD + j];
    }
    if (threadIdx.x < 16) {
        sB1[threadIdx.x] = (threadIdx.x < Hdim) ? bd1[threadIdx.x] : 0.f;
        sB2[threadIdx.x] = bd2[threadIdx.x];
    }
    __syncthreads();

    int tid = blockIdx.x * blockDim.x + threadIdx.x;
    int i = tid >> 3, q = tid & 3, half = (tid >> 2) & 1;
    bool valid = (i < N);
    int ic = valid ? i : 0;

    float4 acc = make_float4(0.f, 0.f, 0.f, 0.f);
    if (valid) acc = csr_agg8(g_Y2, ic, q, half);

    acc.x = fmaxf(acc.x, 0.f); acc.y = fmaxf(acc.y, 0.f);
    acc.z = fmaxf(acc.z, 0.f); acc.w = fmaxf(acc.w, 0.f);

    float h[16];
    group_bcast(acc, h, threadIdx.x & 31);

    int j0 = q * 4;
    float pd[4], pp[4];
#pragma unroll
    for (int d = 0; d < 4; ++d) { pd[d] = sB1[j0 + d]; pp[d] = sB2[j0 + d]; }
#pragma unroll
    for (int k = 0; k < Hdim; ++k) {
        float hk = h[k];
#pragma unroll
        for (int d = 0; d < 4; ++d) {
            pd[d] += hk * sW1[k * 16 + j0 + d];
            pp[d] += hk * sW2[k * 16 + j0 + d];
        }
    }

    if (valid && half == 0) {
        float* o = out + (long)i * OUTC;
#pragma unroll
        for (int d = 0; d < 4; ++d) {
            int j = j0 + d;
            if (j < Hdim) {
                float t = ftanh(pd[d]);
                o[j] = (j < LATC) ? t : fsoftplus(t + SP_INV_1);
            }
            o[Hdim + j] = ftanh(pp[d]);   // 16 perturb outputs: U(14) + m(2)
        }
    }
}

// ---------------- launch ----------------------------------------------------
extern "C" void kernel_launch(void* const* d_in, const int* in_sizes, int n_in,
                              void* d_out, int out_size) {
    const float* X    = (const float*)d_in[0];
    const int*   rows = (const int*)d_in[1];
    const int*   cols = (const int*)d_in[2];
    const float* vals = (const float*)d_in[3];
    const float* W1   = (const float*)d_in[4];
    const float* W2   = (const float*)d_in[5];
    const float* Wd1  = (const float*)d_in[6];
    const float* bd1  = (const float*)d_in[7];
    const float* Wd2  = (const float*)d_in[8];
    const float* bd2  = (const float*)d_in[9];
    float* out = (float*)d_out;

    int N = in_sizes[0] / DIM;
    int E = in_sizes[1];

    const int T = 256;
    int gN  = (N + T - 1) / T;            // node blocks
    int gE  = (E + T - 1) / T;            // edge blocks
    int g8N = (N * 8 + T - 1) / T;        // 8-threads-per-node blocks
    int nb  = (N + 255) / 256;            // scan blocks

    // zero histogram + scan total
    void* cnt_ptr = nullptr;
    cudaGetSymbolAddress(&cnt_ptr, g_cnt);
    cudaMemsetAsync(cnt_ptr, 0, (size_t)(NMAX + 1) * sizeof(int));

    k_fat <<<gN + gE, T>>>(X, W1, rows, N, E, gN);   // gemm1 || histogram
    k_scan<<<nb, 256>>>(N);
    k_fill<<<gE, T>>>(rows, cols, vals, E);
    k_agg1<<<g8N, T>>>(W2, N);
    k_agg2<<<g8N, T>>>(Wd1, bd1, Wd2, bd2, out, N);
}

// round 4
// speedup vs baseline: 1.2165x; 1.2165x over previous
#include <cuda_runtime.h>
#include <math.h>

// Problem constants (fixed by the dataset)
#define NMAX   100000
#define EMAX   1000000
#define DIM    64
#define Hdim   14     // H = 2*LAT
#define PD     16     // P = (LAT+1)*R
#define LATC   7
#define OUTC   30     // 7 loc + 7 scale + 14 U + 2 m
#define SP_INV_1 0.5413248546129181f

// ---------------- scratch (static device globals; no allocation allowed) ---
__device__ float4 g_Y1[NMAX * 4];     // X@W1, padded 16 feats (last 2 = 0)
__device__ float4 g_Y2[NMAX * 4];     // relu(agg1)@W2, padded 16 feats
__device__ int    g_cnt[NMAX + 1];    // degree histogram; [NMAX] = scan total
__device__ int    g_start[NMAX];      // bucket base offsets (disjoint)
__device__ int    g_cursor[NMAX];     // fill cursors (== bucket end after fill)
__device__ int2   g_edge[EMAX];       // (col, val_bits) bucketed by row

// ---------------- K_FAT: gemm1 (blocks < gN) || histogram (rest) -----------
__global__ void k_fat(const float* __restrict__ X, const float* __restrict__ W1,
                      const int* __restrict__ rows, int N, int E, int gN) {
    if ((int)blockIdx.x >= gN) {
        int e = (blockIdx.x - gN) * blockDim.x + threadIdx.x;
        if (e < E) atomicAdd(&g_cnt[rows[e]], 1);
        return;
    }

    // gemm part: Y1 = X @ W1 (N x 64 x 14)
    __shared__ float sW[DIM * Hdim];   // 896 floats
    for (int t = threadIdx.x; t < DIM * Hdim; t += blockDim.x)
        sW[t] = W1[t];
    __syncthreads();

    int i = blockIdx.x * blockDim.x + threadIdx.x;
    if (i >= N) return;

    const float4* x4 = (const float4*)(X + (long)i * DIM);
    float acc[Hdim];
#pragma unroll
    for (int j = 0; j < Hdim; ++j) acc[j] = 0.f;

#pragma unroll
    for (int k4 = 0; k4 < DIM / 4; ++k4) {
        float4 x = x4[k4];
        const float* w = &sW[k4 * 4 * Hdim];
#pragma unroll
        for (int j = 0; j < Hdim; ++j)
            acc[j] += x.x * w[j] + x.y * w[Hdim + j]
                    + x.z * w[2 * Hdim + j] + x.w * w[3 * Hdim + j];
    }

    g_Y1[i * 4 + 0] = make_float4(acc[0], acc[1], acc[2], acc[3]);
    g_Y1[i * 4 + 1] = make_float4(acc[4], acc[5], acc[6], acc[7]);
    g_Y1[i * 4 + 2] = make_float4(acc[8], acc[9], acc[10], acc[11]);
    g_Y1[i * 4 + 3] = make_float4(acc[12], acc[13], 0.f, 0.f);
}

// ---------------- one-pass scan: disjoint bucket bases via atomic total -----
__global__ void k_scan(int N) {
    int t = threadIdx.x;
    int i = blockIdx.x * 256 + t;
    int v = (i < N) ? g_cnt[i] : 0;

    int lane = t & 31, w = t >> 5;
    int x = v;
#pragma unroll
    for (int off = 1; off < 32; off <<= 1) {
        int y = __shfl_up_sync(0xffffffffu, x, off);
        if (lane >= off) x += y;
    }

    __shared__ int wsum[8];
    __shared__ int bbase;
    if (lane == 31) wsum[w] = x;
    __syncthreads();
    if (t < 8) {
        int s = wsum[t];
#pragma unroll
        for (int off = 1; off < 8; off <<= 1) {
            int y = __shfl_up_sync(0xffu, s, off);
            if (t >= off) s += y;
        }
        wsum[t] = s;
        if (t == 7) bbase = atomicAdd(&g_cnt[NMAX], s);  // block base
    }
    __syncthreads();

    if (i < N) {
        int excl = (x - v) + ((w > 0) ? wsum[w - 1] : 0);
        int st = bbase + excl;
        g_start[i]  = st;
        g_cursor[i] = st;
    }
}

__global__ void k_fill(const int* __restrict__ rows, const int* __restrict__ cols,
                       const float* __restrict__ vals, int E) {
    int e = blockIdx.x * blockDim.x + threadIdx.x;
    if (e >= E) return;
    int r = rows[e];
    int pos = atomicAdd(&g_cursor[r], 1);
    g_edge[pos] = make_int2(cols[e], __float_as_int(vals[e]));
}

// ---------------- helpers ---------------------------------------------------
__device__ __forceinline__ float ftanh(float x) {
    x = fminf(fmaxf(x, -15.f), 15.f);
    float e = __expf(2.f * x);
    return (e - 1.f) / (e + 1.f);
}
__device__ __forceinline__ float fsoftplus(float x) {
    return log1pf(__expf(x));   // input range ~[-0.46, 1.54]: safe
}

// 4 lanes per node; lane owns chunk q. Edge loop unrolled x4 for MLP.
__device__ __forceinline__ float4 csr_agg4(const float4* __restrict__ src,
                                           int i, int q) {
    int e   = g_start[i];
    int end = g_cursor[i];     // == start + cnt after fill
    float4 acc = make_float4(0.f, 0.f, 0.f, 0.f);

    for (; e + 4 <= end; e += 4) {
        int2 e0 = __ldg(&g_edge[e + 0]);
        int2 e1 = __ldg(&g_edge[e + 1]);
        int2 e2 = __ldg(&g_edge[e + 2]);
        int2 e3 = __ldg(&g_edge[e + 3]);
        float4 s0 = __ldg(&src[(long)e0.x * 4 + q]);
        float4 s1 = __ldg(&src[(long)e1.x * 4 + q]);
        float4 s2 = __ldg(&src[(long)e2.x * 4 + q]);
        float4 s3 = __ldg(&src[(long)e3.x * 4 + q]);
        float v0 = __int_as_float(e0.y), v1 = __int_as_float(e1.y);
        float v2 = __int_as_float(e2.y), v3 = __int_as_float(e3.y);
        acc.x += v0 * s0.x; acc.y += v0 * s0.y; acc.z += v0 * s0.z; acc.w += v0 * s0.w;
        acc.x += v1 * s1.x; acc.y += v1 * s1.y; acc.z += v1 * s1.z; acc.w += v1 * s1.w;
        acc.x += v2 * s2.x; acc.y += v2 * s2.y; acc.z += v2 * s2.z; acc.w += v2 * s2.w;
        acc.x += v3 * s3.x; acc.y += v3 * s3.y; acc.z += v3 * s3.z; acc.w += v3 * s3.w;
    }
    for (; e < end; ++e) {
        int2 ed = __ldg(&g_edge[e]);
        float v = __int_as_float(ed.y);
        float4 s = __ldg(&src[(long)ed.x * 4 + q]);
        acc.x += v * s.x; acc.y += v * s.y; acc.z += v * s.z; acc.w += v * s.w;
    }
    return acc;
}

// broadcast the 16 h-values of this node's lane-quad into h[16]
__device__ __forceinline__ void group_bcast(float4 acc, float* h, int lane) {
    int base = lane & ~3;
#pragma unroll
    for (int sq = 0; sq < 4; ++sq) {
        h[4 * sq + 0] = __shfl_sync(0xffffffffu, acc.x, base + sq);
        h[4 * sq + 1] = __shfl_sync(0xffffffffu, acc.y, base + sq);
        h[4 * sq + 2] = __shfl_sync(0xffffffffu, acc.z, base + sq);
        h[4 * sq + 3] = __shfl_sync(0xffffffffu, acc.w, base + sq);
    }
}

// ---------------- K_AGG1: Y2 = relu(agg(Y1)) @ W2 (fused) ------------------
__global__ void k_agg1(const float* __restrict__ W2, int N) {
    __shared__ float sW[Hdim * 16];    // W2 padded to 14x16, pads = 0
    for (int t = threadIdx.x; t < Hdim * 16; t += blockDim.x) {
        int k = t >> 4, j = t & 15;
        sW[t] = (j < Hdim) ? W2[k * Hdim + j] : 0.f;
    }
    __syncthreads();

    int tid = blockIdx.x * blockDim.x + threadIdx.x;
    int i = tid >> 2, q = tid & 3;
    bool valid = (i < N);
    int ic = valid ? i : 0;

    float4 acc = make_float4(0.f, 0.f, 0.f, 0.f);
    if (valid) acc = csr_agg4(g_Y1, ic, q);

    acc.x = fmaxf(acc.x, 0.f); acc.y = fmaxf(acc.y, 0.f);
    acc.z = fmaxf(acc.z, 0.f); acc.w = fmaxf(acc.w, 0.f);

    float h[16];
    group_bcast(acc, h, threadIdx.x & 31);

    int j0 = q * 4;
    float y[4] = {0.f, 0.f, 0.f, 0.f};
#pragma unroll
    for (int k = 0; k < Hdim; ++k) {
        float hk = h[k];
#pragma unroll
        for (int d = 0; d < 4; ++d)
            y[d] += hk * sW[k * 16 + j0 + d];
    }

    if (valid)
        g_Y2[(long)i * 4 + q] = make_float4(y[0], y[1], y[2], y[3]);
}

// ---------------- K_AGG2: agg(Y2) -> relu -> heads -> out (fused) ----------
__global__ void k_agg2(const float* __restrict__ Wd1, const float* __restrict__ bd1,
                       const float* __restrict__ Wd2, const float* __restrict__ bd2,
                       float* __restrict__ out, int N) {
    __shared__ float sW1[Hdim * 16];   // Wd1 padded 14x16
    __shared__ float sW2[Hdim * 16];   // Wd2 14x16 (natural)
    __shared__ float sB1[16];
    __shared__ float sB2[16];
    for (int t = threadIdx.x; t < Hdim * 16; t += blockDim.x) {
        int k = t >> 4, j = t & 15;
        sW1[t] = (j < Hdim) ? Wd1[k * Hdim + j] : 0.f;
        sW2[t] = Wd2[k * PD + j];
    }
    if (threadIdx.x < 16) {
        sB1[threadIdx.x] = (threadIdx.x < Hdim) ? bd1[threadIdx.x] : 0.f;
        sB2[threadIdx.x] = bd2[threadIdx.x];
    }
    __syncthreads();

    int tid = blockIdx.x * blockDim.x + threadIdx.x;
    int i = tid >> 2, q = tid & 3;
    bool valid = (i < N);
    int ic = valid ? i : 0;

    float4 acc = make_float4(0.f, 0.f, 0.f, 0.f);
    if (valid) acc = csr_agg4(g_Y2, ic, q);

    acc.x = fmaxf(acc.x, 0.f); acc.y = fmaxf(acc.y, 0.f);
    acc.z = fmaxf(acc.z, 0.f); acc.w = fmaxf(acc.w, 0.f);

    float h[16];
    group_bcast(acc, h, threadIdx.x & 31);

    int j0 = q * 4;
    float pd[4], pp[4];
#pragma unroll
    for (int d = 0; d < 4; ++d) { pd[d] = sB1[j0 + d]; pp[d] = sB2[j0 + d]; }
#pragma unroll
    for (int k = 0; k < Hdim; ++k) {
        float hk = h[k];
#pragma unroll
        for (int d = 0; d < 4; ++d) {
            pd[d] += hk * sW1[k * 16 + j0 + d];
            pp[d] += hk * sW2[k * 16 + j0 + d];
        }
    }

    if (valid) {
        float* o = out + (long)i * OUTC;
#pragma unroll
        for (int d = 0; d < 4; ++d) {
            int j = j0 + d;
            if (j < Hdim) {
                float t = ftanh(pd[d]);
                o[j] = (j < LATC) ? t : fsoftplus(t + SP_INV_1);
            }
            o[Hdim + j] = ftanh(pp[d]);   // 16 perturb outputs: U(14) + m(2)
        }
    }
}

// ---------------- launch ----------------------------------------------------
extern "C" void kernel_launch(void* const* d_in, const int* in_sizes, int n_in,
                              void* d_out, int out_size) {
    const float* X    = (const float*)d_in[0];
    const int*   rows = (const int*)d_in[1];
    const int*   cols = (const int*)d_in[2];
    const float* vals = (const float*)d_in[3];
    const float* W1   = (const float*)d_in[4];
    const float* W2   = (const float*)d_in[5];
    const float* Wd1  = (const float*)d_in[6];
    const float* bd1  = (const float*)d_in[7];
    const float* Wd2  = (const float*)d_in[8];
    const float* bd2  = (const float*)d_in[9];
    float* out = (float*)d_out;

    int N = in_sizes[0] / DIM;
    int E = in_sizes[1];

    const int T = 256;
    int gN  = (N + T - 1) / T;            // node blocks
    int gE  = (E + T - 1) / T;            // edge blocks
    int g4N = (N * 4 + T - 1) / T;        // 4-threads-per-node blocks
    int nb  = (N + 255) / 256;            // scan blocks

    // zero histogram + scan total
    void* cnt_ptr = nullptr;
    cudaGetSymbolAddress(&cnt_ptr, g_cnt);
    cudaMemsetAsync(cnt_ptr, 0, (size_t)(NMAX + 1) * sizeof(int));

    k_fat <<<gN + gE, T>>>(X, W1, rows, N, E, gN);   // gemm1 || histogram
    k_scan<<<nb, 256>>>(N);
    k_fill<<<gE, T>>>(rows, cols, vals, E);
    k_agg1<<<g4N, T>>>(W2, N);
    k_agg2<<<g4N, T>>>(Wd1, bd1, Wd2, bd2, out, N);
}

// round 5
// speedup vs baseline: 1.2559x; 1.0324x over previous
#include <cuda_runtime.h>
#include <math.h>

// Problem constants (fixed by the dataset)
#define NMAX   100000
#define EMAX   1000000
#define DIM    64
#define Hdim   14     // H = 2*LAT
#define PD     16     // P = (LAT+1)*R
#define LATC   7
#define OUTC   30     // 7 loc + 7 scale + 14 U + 2 m
#define SP_INV_1 0.5413248546129181f

// ---------------- scratch (static device globals; no allocation allowed) ---
__device__ float4 g_Y1[NMAX * 4];     // X@W1, padded 16 feats (last 2 = 0)
__device__ float4 g_Y2[NMAX * 4];     // relu(agg1)@W2, padded 16 feats
__device__ int    g_cnt[NMAX + 1];    // degree histogram; [NMAX] = scan total
__device__ int    g_start[NMAX];      // bucket base offsets (disjoint)
__device__ int    g_rank[EMAX];       // within-row rank of each edge
__device__ int2   g_edge[EMAX];       // (col, val_bits) bucketed by row

// ---------------- K_FAT: gemm1 (blocks < gN) || histogram+rank (rest) ------
__global__ void k_fat(const float* __restrict__ X, const float* __restrict__ W1,
                      const int* __restrict__ rows, int N, int E, int gN) {
    if ((int)blockIdx.x >= gN) {
        int e = (blockIdx.x - gN) * blockDim.x + threadIdx.x;
        if (e < E) {
            int rk = atomicAdd(&g_cnt[rows[e]], 1);
            g_rank[e] = rk;
        }
        return;
    }

    // gemm part: Y1 = X @ W1 (N x 64 x 14)
    __shared__ float sW[DIM * Hdim];   // 896 floats
    for (int t = threadIdx.x; t < DIM * Hdim; t += blockDim.x)
        sW[t] = W1[t];
    __syncthreads();

    int i = blockIdx.x * blockDim.x + threadIdx.x;
    if (i >= N) return;

    const float4* x4 = (const float4*)(X + (long)i * DIM);
    float acc[Hdim];
#pragma unroll
    for (int j = 0; j < Hdim; ++j) acc[j] = 0.f;

#pragma unroll
    for (int k4 = 0; k4 < DIM / 4; ++k4) {
        float4 x = x4[k4];
        const float* w = &sW[k4 * 4 * Hdim];
#pragma unroll
        for (int j = 0; j < Hdim; ++j)
            acc[j] += x.x * w[j] + x.y * w[Hdim + j]
                    + x.z * w[2 * Hdim + j] + x.w * w[3 * Hdim + j];
    }

    g_Y1[i * 4 + 0] = make_float4(acc[0], acc[1], acc[2], acc[3]);
    g_Y1[i * 4 + 1] = make_float4(acc[4], acc[5], acc[6], acc[7]);
    g_Y1[i * 4 + 2] = make_float4(acc[8], acc[9], acc[10], acc[11]);
    g_Y1[i * 4 + 3] = make_float4(acc[12], acc[13], 0.f, 0.f);
}

// ---------------- one-pass scan: disjoint bucket bases via atomic total -----
__global__ void k_scan(int N) {
    int t = threadIdx.x;
    int i = blockIdx.x * 256 + t;
    int v = (i < N) ? g_cnt[i] : 0;

    int lane = t & 31, w = t >> 5;
    int x = v;
#pragma unroll
    for (int off = 1; off < 32; off <<= 1) {
        int y = __shfl_up_sync(0xffffffffu, x, off);
        if (lane >= off) x += y;
    }

    __shared__ int wsum[8];
    __shared__ int bbase;
    if (lane == 31) wsum[w] = x;
    __syncthreads();
    if (t < 8) {
        int s = wsum[t];
#pragma unroll
        for (int off = 1; off < 8; off <<= 1) {
            int y = __shfl_up_sync(0xffu, s, off);
            if (t >= off) s += y;
        }
        wsum[t] = s;
        if (t == 7) bbase = atomicAdd(&g_cnt[NMAX], s);  // block base
    }
    __syncthreads();

    if (i < N) {
        int excl = (x - v) + ((w > 0) ? wsum[w - 1] : 0);
        g_start[i] = bbase + excl;
    }
}

// atomic-free scatter using precomputed ranks
__global__ void k_fill(const int* __restrict__ rows, const int* __restrict__ cols,
                       const float* __restrict__ vals, int E) {
    int e = blockIdx.x * blockDim.x + threadIdx.x;
    if (e >= E) return;
    int r = rows[e];
    int pos = g_start[r] + g_rank[e];
    g_edge[pos] = make_int2(cols[e], __float_as_int(vals[e]));
}

// ---------------- helpers ---------------------------------------------------
__device__ __forceinline__ float ftanh(float x) {
    x = fminf(fmaxf(x, -15.f), 15.f);
    float e = __expf(2.f * x);
    return (e - 1.f) / (e + 1.f);
}
__device__ __forceinline__ float fsoftplus(float x) {
    return log1pf(__expf(x));   // input range ~[-0.46, 1.54]: safe
}

// 4 lanes per node; lane owns chunk q. Edge loop unrolled x4 for MLP.
__device__ __forceinline__ float4 csr_agg4(const float4* __restrict__ src,
                                           int i, int q) {
    int e   = g_start[i];
    int end = e + g_cnt[i];
    float4 acc = make_float4(0.f, 0.f, 0.f, 0.f);

    for (; e + 4 <= end; e += 4) {
        int2 e0 = __ldg(&g_edge[e + 0]);
        int2 e1 = __ldg(&g_edge[e + 1]);
        int2 e2 = __ldg(&g_edge[e + 2]);
        int2 e3 = __ldg(&g_edge[e + 3]);
        float4 s0 = __ldg(&src[(long)e0.x * 4 + q]);
        float4 s1 = __ldg(&src[(long)e1.x * 4 + q]);
        float4 s2 = __ldg(&src[(long)e2.x * 4 + q]);
        float4 s3 = __ldg(&src[(long)e3.x * 4 + q]);
        float v0 = __int_as_float(e0.y), v1 = __int_as_float(e1.y);
        float v2 = __int_as_float(e2.y), v3 = __int_as_float(e3.y);
        acc.x += v0 * s0.x; acc.y += v0 * s0.y; acc.z += v0 * s0.z; acc.w += v0 * s0.w;
        acc.x += v1 * s1.x; acc.y += v1 * s1.y; acc.z += v1 * s1.z; acc.w += v1 * s1.w;
        acc.x += v2 * s2.x; acc.y += v2 * s2.y; acc.z += v2 * s2.z; acc.w += v2 * s2.w;
        acc.x += v3 * s3.x; acc.y += v3 * s3.y; acc.z += v3 * s3.z; acc.w += v3 * s3.w;
    }
    for (; e < end; ++e) {
        int2 ed = __ldg(&g_edge[e]);
        float v = __int_as_float(ed.y);
        float4 s = __ldg(&src[(long)ed.x * 4 + q]);
        acc.x += v * s.x; acc.y += v * s.y; acc.z += v * s.z; acc.w += v * s.w;
    }
    return acc;
}

// broadcast the 16 h-values of this node's lane-quad into h[16]
__device__ __forceinline__ void group_bcast(float4 acc, float* h, int lane) {
    int base = lane & ~3;
#pragma unroll
    for (int sq = 0; sq < 4; ++sq) {
        h[4 * sq + 0] = __shfl_sync(0xffffffffu, acc.x, base + sq);
        h[4 * sq + 1] = __shfl_sync(0xffffffffu, acc.y, base + sq);
        h[4 * sq + 2] = __shfl_sync(0xffffffffu, acc.z, base + sq);
        h[4 * sq + 3] = __shfl_sync(0xffffffffu, acc.w, base + sq);
    }
}

// ---------------- K_AGG1: Y2 = relu(agg(Y1)) @ W2 (fused) ------------------
__global__ void __launch_bounds__(256, 8) k_agg1(const float* __restrict__ W2, int N) {
    __shared__ float sW[Hdim * 16];    // W2 padded to 14x16, pads = 0
    for (int t = threadIdx.x; t < Hdim * 16; t += blockDim.x) {
        int k = t >> 4, j = t & 15;
        sW[t] = (j < Hdim) ? W2[k * Hdim + j] : 0.f;
    }
    __syncthreads();

    int tid = blockIdx.x * blockDim.x + threadIdx.x;
    int i = tid >> 2, q = tid & 3;
    bool valid = (i < N);
    int ic = valid ? i : 0;

    float4 acc = make_float4(0.f, 0.f, 0.f, 0.f);
    if (valid) acc = csr_agg4(g_Y1, ic, q);

    acc.x = fmaxf(acc.x, 0.f); acc.y = fmaxf(acc.y, 0.f);
    acc.z = fmaxf(acc.z, 0.f); acc.w = fmaxf(acc.w, 0.f);

    float h[16];
    group_bcast(acc, h, threadIdx.x & 31);

    int j0 = q * 4;
    float y[4] = {0.f, 0.f, 0.f, 0.f};
#pragma unroll
    for (int k = 0; k < Hdim; ++k) {
        float hk = h[k];
#pragma unroll
        for (int d = 0; d < 4; ++d)
            y[d] += hk * sW[k * 16 + j0 + d];
    }

    if (valid)
        g_Y2[(long)i * 4 + q] = make_float4(y[0], y[1], y[2], y[3]);
}

// ---------------- K_AGG2: agg(Y2) -> relu -> heads -> out (fused) ----------
__global__ void __launch_bounds__(256, 8) k_agg2(
                       const float* __restrict__ Wd1, const float* __restrict__ bd1,
                       const float* __restrict__ Wd2, const float* __restrict__ bd2,
                       float* __restrict__ out, int N) {
    __shared__ float sW1[Hdim * 16];   // Wd1 padded 14x16
    __shared__ float sW2[Hdim * 16];   // Wd2 14x16 (natural)
    __shared__ float sB1[16];
    __shared__ float sB2[16];
    for (int t = threadIdx.x; t < Hdim * 16; t += blockDim.x) {
        int k = t >> 4, j = t & 15;
        sW1[t] = (j < Hdim) ? Wd1[k * Hdim + j] : 0.f;
        sW2[t] = Wd2[k * PD + j];
    }
    if (threadIdx.x < 16) {
        sB1[threadIdx.x] = (threadIdx.x < Hdim) ? bd1[threadIdx.x] : 0.f;
        sB2[threadIdx.x] = bd2[threadIdx.x];
    }
    __syncthreads();

    int tid = blockIdx.x * blockDim.x + threadIdx.x;
    int i = tid >> 2, q = tid & 3;
    bool valid = (i < N);
    int ic = valid ? i : 0;

    float4 acc = make_float4(0.f, 0.f, 0.f, 0.f);
    if (valid) acc = csr_agg4(g_Y2, ic, q);

    acc.x = fmaxf(acc.x, 0.f); acc.y = fmaxf(acc.y, 0.f);
    acc.z = fmaxf(acc.z, 0.f); acc.w = fmaxf(acc.w, 0.f);

    float h[16];
    group_bcast(acc, h, threadIdx.x & 31);

    int j0 = q * 4;
    float pd[4], pp[4];
#pragma unroll
    for (int d = 0; d < 4; ++d) { pd[d] = sB1[j0 + d]; pp[d] = sB2[j0 + d]; }
#pragma unroll
    for (int k = 0; k < Hdim; ++k) {
        float hk = h[k];
#pragma unroll
        for (int d = 0; d < 4; ++d) {
            pd[d] += hk * sW1[k * 16 + j0 + d];
            pp[d] += hk * sW2[k * 16 + j0 + d];
        }
    }

    if (valid) {
        float* o = out + (long)i * OUTC;
#pragma unroll
        for (int d = 0; d < 4; ++d) {
            int j = j0 + d;
            if (j < Hdim) {
                float t = ftanh(pd[d]);
                o[j] = (j < LATC) ? t : fsoftplus(t + SP_INV_1);
            }
            o[Hdim + j] = ftanh(pp[d]);   // 16 perturb outputs: U(14) + m(2)
        }
    }
}

// ---------------- launch ----------------------------------------------------
extern "C" void kernel_launch(void* const* d_in, const int* in_sizes, int n_in,
                              void* d_out, int out_size) {
    const float* X    = (const float*)d_in[0];
    const int*   rows = (const int*)d_in[1];
    const int*   cols = (const int*)d_in[2];
    const float* vals = (const float*)d_in[3];
    const float* W1   = (const float*)d_in[4];
    const float* W2   = (const float*)d_in[5];
    const float* Wd1  = (const float*)d_in[6];
    const float* bd1  = (const float*)d_in[7];
    const float* Wd2  = (const float*)d_in[8];
    const float* bd2  = (const float*)d_in[9];
    float* out = (float*)d_out;

    int N = in_sizes[0] / DIM;
    int E = in_sizes[1];

    const int T = 256;
    int gN  = (N + T - 1) / T;            // node blocks
    int gE  = (E + T - 1) / T;            // edge blocks
    int g4N = (N * 4 + T - 1) / T;        // 4-threads-per-node blocks
    int nb  = (N + 255) / 256;            // scan blocks

    // zero histogram + scan total
    void* cnt_ptr = nullptr;
    cudaGetSymbolAddress(&cnt_ptr, g_cnt);
    cudaMemsetAsync(cnt_ptr, 0, (size_t)(NMAX + 1) * sizeof(int));

    k_fat <<<gN + gE, T>>>(X, W1, rows, N, E, gN);   // gemm1 || histogram+rank
    k_scan<<<nb, 256>>>(N);
    k_fill<<<gE, T>>>(rows, cols, vals, E);
    k_agg1<<<g4N, T>>>(W2, N);
    k_agg2<<<g4N, T>>>(Wd1, bd1, Wd2, bd2, out, N);
}

// round 6
// speedup vs baseline: 1.2564x; 1.0004x over previous
#include <cuda_runtime.h>
#include <math.h>

// Problem constants (fixed by the dataset)
#define NMAX   100000
#define EMAX   1000000
#define DIM    64
#define Hdim   14     // H = 2*LAT
#define PD     16     // P = (LAT+1)*R
#define LATC   7
#define OUTC   30     // 7 loc + 7 scale + 14 U + 2 m
#define SP_INV_1 0.5413248546129181f

// ---------------- scratch (static device globals; no allocation allowed) ---
__device__ float4 g_Y1[NMAX * 4];     // X@W1, padded 16 feats (last 2 = 0)
__device__ float4 g_Y2[NMAX * 4];     // relu(agg1)@W2, padded 16 feats
__device__ int    g_cnt[NMAX + 1];    // degree histogram; [NMAX] = scan total
__device__ int    g_start[NMAX];      // bucket base offsets (disjoint)
__device__ int    g_rank[EMAX];       // within-row rank of each edge
__device__ int2   g_edge[EMAX];       // (col, val_bits) bucketed by row

// ---------------- K_FAT: gemm1 (blocks < gN) || histogram+rank (rest) ------
__global__ void k_fat(const float* __restrict__ X, const float* __restrict__ W1,
                      const int* __restrict__ rows, int N, int E, int gN) {
    if ((int)blockIdx.x >= gN) {
        int e = (blockIdx.x - gN) * blockDim.x + threadIdx.x;
        if (e < E) {
            int rk = atomicAdd(&g_cnt[rows[e]], 1);
            g_rank[e] = rk;
        }
        return;
    }

    // gemm part: Y1 = X @ W1 (N x 64 x 14)
    __shared__ float sW[DIM * Hdim];   // 896 floats
    for (int t = threadIdx.x; t < DIM * Hdim; t += blockDim.x)
        sW[t] = W1[t];
    __syncthreads();

    int i = blockIdx.x * blockDim.x + threadIdx.x;
    if (i >= N) return;

    const float4* x4 = (const float4*)(X + (long)i * DIM);
    float acc[Hdim];
#pragma unroll
    for (int j = 0; j < Hdim; ++j) acc[j] = 0.f;

#pragma unroll
    for (int k4 = 0; k4 < DIM / 4; ++k4) {
        float4 x = x4[k4];
        const float* w = &sW[k4 * 4 * Hdim];
#pragma unroll
        for (int j = 0; j < Hdim; ++j)
            acc[j] += x.x * w[j] + x.y * w[Hdim + j]
                    + x.z * w[2 * Hdim + j] + x.w * w[3 * Hdim + j];
    }

    g_Y1[i * 4 + 0] = make_float4(acc[0], acc[1], acc[2], acc[3]);
    g_Y1[i * 4 + 1] = make_float4(acc[4], acc[5], acc[6], acc[7]);
    g_Y1[i * 4 + 2] = make_float4(acc[8], acc[9], acc[10], acc[11]);
    g_Y1[i * 4 + 3] = make_float4(acc[12], acc[13], 0.f, 0.f);
}

// ---------------- one-pass scan: disjoint bucket bases via atomic total -----
__global__ void k_scan(int N) {
    int t = threadIdx.x;
    int i = blockIdx.x * 256 + t;
    int v = (i < N) ? g_cnt[i] : 0;

    int lane = t & 31, w = t >> 5;
    int x = v;
#pragma unroll
    for (int off = 1; off < 32; off <<= 1) {
        int y = __shfl_up_sync(0xffffffffu, x, off);
        if (lane >= off) x += y;
    }

    __shared__ int wsum[8];
    __shared__ int bbase;
    if (lane == 31) wsum[w] = x;
    __syncthreads();
    if (t < 8) {
        int s = wsum[t];
#pragma unroll
        for (int off = 1; off < 8; off <<= 1) {
            int y = __shfl_up_sync(0xffu, s, off);
            if (t >= off) s += y;
        }
        wsum[t] = s;
        if (t == 7) bbase = atomicAdd(&g_cnt[NMAX], s);  // block base
    }
    __syncthreads();

    if (i < N) {
        int excl = (x - v) + ((w > 0) ? wsum[w - 1] : 0);
        g_start[i] = bbase + excl;
    }
}

// atomic-free scatter using precomputed ranks
__global__ void k_fill(const int* __restrict__ rows, const int* __restrict__ cols,
                       const float* __restrict__ vals, int E) {
    int e = blockIdx.x * blockDim.x + threadIdx.x;
    if (e >= E) return;
    int r = rows[e];
    int pos = g_start[r] + g_rank[e];
    g_edge[pos] = make_int2(cols[e], __float_as_int(vals[e]));
}

// ---------------- helpers ---------------------------------------------------
__device__ __forceinline__ float ftanh(float x) {
    x = fminf(fmaxf(x, -15.f), 15.f);
    float e = __expf(2.f * x);
    return (e - 1.f) / (e + 1.f);
}
__device__ __forceinline__ float fsoftplus(float x) {
    return log1pf(__expf(x));   // input range ~[-0.46, 1.54]: safe
}

// 4 lanes per node; lane owns chunk q. Edge loop unrolled x8 then x4 for MLP.
__device__ __forceinline__ float4 csr_agg4(const float4* __restrict__ src,
                                           int i, int q) {
    int e   = g_start[i];
    int end = e + g_cnt[i];
    float4 acc = make_float4(0.f, 0.f, 0.f, 0.f);

    for (; e + 8 <= end; e += 8) {
        int2 ed[8];
#pragma unroll
        for (int u = 0; u < 8; ++u) ed[u] = __ldg(&g_edge[e + u]);
        float4 s[8];
#pragma unroll
        for (int u = 0; u < 8; ++u) s[u] = __ldg(&src[(long)ed[u].x * 4 + q]);
#pragma unroll
        for (int u = 0; u < 8; ++u) {
            float v = __int_as_float(ed[u].y);
            acc.x += v * s[u].x; acc.y += v * s[u].y;
            acc.z += v * s[u].z; acc.w += v * s[u].w;
        }
    }
    if (e + 4 <= end) {
        int2 ed[4];
#pragma unroll
        for (int u = 0; u < 4; ++u) ed[u] = __ldg(&g_edge[e + u]);
        float4 s[4];
#pragma unroll
        for (int u = 0; u < 4; ++u) s[u] = __ldg(&src[(long)ed[u].x * 4 + q]);
#pragma unroll
        for (int u = 0; u < 4; ++u) {
            float v = __int_as_float(ed[u].y);
            acc.x += v * s[u].x; acc.y += v * s[u].y;
            acc.z += v * s[u].z; acc.w += v * s[u].w;
        }
        e += 4;
    }
    for (; e < end; ++e) {
        int2 ed = __ldg(&g_edge[e]);
        float v = __int_as_float(ed.y);
        float4 s = __ldg(&src[(long)ed.x * 4 + q]);
        acc.x += v * s.x; acc.y += v * s.y; acc.z += v * s.z; acc.w += v * s.w;
    }
    return acc;
}

// broadcast the 16 h-values of this node's lane-quad into h[16]
__device__ __forceinline__ void group_bcast(float4 acc, float* h, int lane) {
    int base = lane & ~3;
#pragma unroll
    for (int sq = 0; sq < 4; ++sq) {
        h[4 * sq + 0] = __shfl_sync(0xffffffffu, acc.x, base + sq);
        h[4 * sq + 1] = __shfl_sync(0xffffffffu, acc.y, base + sq);
        h[4 * sq + 2] = __shfl_sync(0xffffffffu, acc.z, base + sq);
        h[4 * sq + 3] = __shfl_sync(0xffffffffu, acc.w, base + sq);
    }
}

// ---------------- K_AGG1: Y2 = relu(agg(Y1)) @ W2 (fused) ------------------
__global__ void k_agg1(const float* __restrict__ W2, int N) {
    __shared__ float sW[Hdim * 16];    // W2 padded to 14x16, pads = 0
    for (int t = threadIdx.x; t < Hdim * 16; t += blockDim.x) {
        int k = t >> 4, j = t & 15;
        sW[t] = (j < Hdim) ? W2[k * Hdim + j] : 0.f;
    }
    __syncthreads();

    int tid = blockIdx.x * blockDim.x + threadIdx.x;
    int i = tid >> 2, q = tid & 3;
    bool valid = (i < N);
    int ic = valid ? i : 0;

    float4 acc = make_float4(0.f, 0.f, 0.f, 0.f);
    if (valid) acc = csr_agg4(g_Y1, ic, q);

    acc.x = fmaxf(acc.x, 0.f); acc.y = fmaxf(acc.y, 0.f);
    acc.z = fmaxf(acc.z, 0.f); acc.w = fmaxf(acc.w, 0.f);

    float h[16];
    group_bcast(acc, h, threadIdx.x & 31);

    int j0 = q * 4;
    float y[4] = {0.f, 0.f, 0.f, 0.f};
#pragma unroll
    for (int k = 0; k < Hdim; ++k) {
        float hk = h[k];
#pragma unroll
        for (int d = 0; d < 4; ++d)
            y[d] += hk * sW[k * 16 + j0 + d];
    }

    if (valid)
        g_Y2[(long)i * 4 + q] = make_float4(y[0], y[1], y[2], y[3]);
}

// ---------------- K_AGG2: agg(Y2) -> relu -> heads -> out (fused) ----------
__global__ void k_agg2(const float* __restrict__ Wd1, const float* __restrict__ bd1,
                       const float* __restrict__ Wd2, const float* __restrict__ bd2,
                       float* __restrict__ out, int N) {
    __shared__ float sW1[Hdim * 16];   // Wd1 padded 14x16
    __shared__ float sW2[Hdim * 16];   // Wd2 14x16 (natural)
    __shared__ float sB1[16];
    __shared__ float sB2[16];
    for (int t = threadIdx.x; t < Hdim * 16; t += blockDim.x) {
        int k = t >> 4, j = t & 15;
        sW1[t] = (j < Hdim) ? Wd1[k * Hdim + j] : 0.f;
        sW2[t] = Wd2[k * PD + j];
    }
    if (threadIdx.x < 16) {
        sB1[threadIdx.x] = (threadIdx.x < Hdim) ? bd1[threadIdx.x] : 0.f;
        sB2[threadIdx.x] = bd2[threadIdx.x];
    }
    __syncthreads();

    int tid = blockIdx.x * blockDim.x + threadIdx.x;
    int i = tid >> 2, q = tid & 3;
    bool valid = (i < N);
    int ic = valid ? i : 0;

    float4 acc = make_float4(0.f, 0.f, 0.f, 0.f);
    if (valid) acc = csr_agg4(g_Y2, ic, q);

    acc.x = fmaxf(acc.x, 0.f); acc.y = fmaxf(acc.y, 0.f);
    acc.z = fmaxf(acc.z, 0.f); acc.w = fmaxf(acc.w, 0.f);

    float h[16];
    group_bcast(acc, h, threadIdx.x & 31);

    int j0 = q * 4;
    float pd[4], pp[4];
#pragma unroll
    for (int d = 0; d < 4; ++d) { pd[d] = sB1[j0 + d]; pp[d] = sB2[j0 + d]; }
#pragma unroll
    for (int k = 0; k < Hdim; ++k) {
        float hk = h[k];
#pragma unroll
        for (int d = 0; d < 4; ++d) {
            pd[d] += hk * sW1[k * 16 + j0 + d];
            pp[d] += hk * sW2[k * 16 + j0 + d];
        }
    }

    if (valid) {
        float* o = out + (long)i * OUTC;
#pragma unroll
        for (int d = 0; d < 4; ++d) {
            int j = j0 + d;
            if (j < Hdim) {
                float t = ftanh(pd[d]);
                o[j] = (j < LATC) ? t : fsoftplus(t + SP_INV_1);
            }
            o[Hdim + j] = ftanh(pp[d]);   // 16 perturb outputs: U(14) + m(2)
        }
    }
}

// ---------------- launch ----------------------------------------------------
extern "C" void kernel_launch(void* const* d_in, const int* in_sizes, int n_in,
                              void* d_out, int out_size) {
    const float* X    = (const float*)d_in[0];
    const int*   rows = (const int*)d_in[1];
    const int*   cols = (const int*)d_in[2];
    const float* vals = (const float*)d_in[3];
    const float* W1   = (const float*)d_in[4];
    const float* W2   = (const float*)d_in[5];
    const float* Wd1  = (const float*)d_in[6];
    const float* bd1  = (const float*)d_in[7];
    const float* Wd2  = (const float*)d_in[8];
    const float* bd2  = (const float*)d_in[9];
    float* out = (float*)d_out;

    int N = in_sizes[0] / DIM;
    int E = in_sizes[1];

    const int T = 256;
    int gN  = (N + T - 1) / T;            // node blocks
    int gE  = (E + T - 1) / T;            // edge blocks
    int g4N = (N * 4 + T - 1) / T;        // 4-threads-per-node blocks
    int nb  = (N + 255) / 256;            // scan blocks

    // zero histogram + scan total
    void* cnt_ptr = nullptr;
    cudaGetSymbolAddress(&cnt_ptr, g_cnt);
    cudaMemsetAsync(cnt_ptr, 0, (size_t)(NMAX + 1) * sizeof(int));

    k_fat <<<gN + gE, T>>>(X, W1, rows, N, E, gN);   // gemm1 || histogram+rank
    k_scan<<<nb, 256>>>(N);
    k_fill<<<gE, T>>>(rows, cols, vals, E);
    k_agg1<<<g4N, T>>>(W2, N);
    k_agg2<<<g4N, T>>>(Wd1, bd1, Wd2, bd2, out, N);
}

// round 7
// speedup vs baseline: 1.3265x; 1.0557x over previous
#include <cuda_runtime.h>
#include <cuda_fp16.h>
#include <math.h>

// Problem constants (fixed by the dataset)
#define NMAX   100000
#define EMAX   1000000
#define DIM    64
#define Hdim   14     // H = 2*LAT
#define PD     16     // P = (LAT+1)*R
#define LATC   7
#define OUTC   30     // 7 loc + 7 scale + 14 U + 2 m
#define SP_INV_1 0.5413248546129181f

// ---------------- scratch (static device globals; no allocation allowed) ---
// features stored as fp16: node row = 16 halves = 32B = 4 lanes x uint2
__device__ uint2  g_Y1h[NMAX * 4];    // X@W1 (fp16, padded 16 feats, pads=0)
__device__ uint2  g_Y2h[NMAX * 4];    // relu(agg1)@W2 (fp16)
__device__ int    g_cnt[NMAX + 1];    // degree histogram; [NMAX] = scan total
__device__ int    g_start[NMAX];      // bucket base offsets (disjoint)
__device__ int    g_rank[EMAX];       // within-row rank of each edge
__device__ int2   g_edge[EMAX];       // (col, val_bits) bucketed by row

// pack 4 fp32 -> uint2 of half2
__device__ __forceinline__ uint2 pack4h(float a, float b, float c, float d) {
    half2 lo = __floats2half2_rn(a, b);
    half2 hi = __floats2half2_rn(c, d);
    uint2 r;
    r.x = *reinterpret_cast<unsigned*>(&lo);
    r.y = *reinterpret_cast<unsigned*>(&hi);
    return r;
}

// ---------------- K_FAT: gemm1 (blocks < gN) || histogram+rank (rest) ------
__global__ void k_fat(const float* __restrict__ X, const float* __restrict__ W1,
                      const int* __restrict__ rows, int N, int E, int gN) {
    if ((int)blockIdx.x >= gN) {
        int e = (blockIdx.x - gN) * blockDim.x + threadIdx.x;
        if (e < E) {
            int rk = atomicAdd(&g_cnt[rows[e]], 1);
            g_rank[e] = rk;
        }
        return;
    }

    // gemm part: Y1 = X @ W1 (N x 64 x 14)
    __shared__ float sW[DIM * Hdim];   // 896 floats
    for (int t = threadIdx.x; t < DIM * Hdim; t += blockDim.x)
        sW[t] = W1[t];
    __syncthreads();

    int i = blockIdx.x * blockDim.x + threadIdx.x;
    if (i >= N) return;

    const float4* x4 = (const float4*)(X + (long)i * DIM);
    float acc[Hdim];
#pragma unroll
    for (int j = 0; j < Hdim; ++j) acc[j] = 0.f;

#pragma unroll
    for (int k4 = 0; k4 < DIM / 4; ++k4) {
        float4 x = x4[k4];
        const float* w = &sW[k4 * 4 * Hdim];
#pragma unroll
        for (int j = 0; j < Hdim; ++j)
            acc[j] += x.x * w[j] + x.y * w[Hdim + j]
                    + x.z * w[2 * Hdim + j] + x.w * w[3 * Hdim + j];
    }

    g_Y1h[i * 4 + 0] = pack4h(acc[0], acc[1], acc[2], acc[3]);
    g_Y1h[i * 4 + 1] = pack4h(acc[4], acc[5], acc[6], acc[7]);
    g_Y1h[i * 4 + 2] = pack4h(acc[8], acc[9], acc[10], acc[11]);
    g_Y1h[i * 4 + 3] = pack4h(acc[12], acc[13], 0.f, 0.f);
}

// ---------------- one-pass scan: disjoint bucket bases via atomic total -----
__global__ void k_scan(int N) {
    int t = threadIdx.x;
    int i = blockIdx.x * 256 + t;
    int v = (i < N) ? g_cnt[i] : 0;

    int lane = t & 31, w = t >> 5;
    int x = v;
#pragma unroll
    for (int off = 1; off < 32; off <<= 1) {
        int y = __shfl_up_sync(0xffffffffu, x, off);
        if (lane >= off) x += y;
    }

    __shared__ int wsum[8];
    __shared__ int bbase;
    if (lane == 31) wsum[w] = x;
    __syncthreads();
    if (t < 8) {
        int s = wsum[t];
#pragma unroll
        for (int off = 1; off < 8; off <<= 1) {
            int y = __shfl_up_sync(0xffu, s, off);
            if (t >= off) s += y;
        }
        wsum[t] = s;
        if (t == 7) bbase = atomicAdd(&g_cnt[NMAX], s);  // block base
    }
    __syncthreads();

    if (i < N) {
        int excl = (x - v) + ((w > 0) ? wsum[w - 1] : 0);
        g_start[i] = bbase + excl;
    }
}

// atomic-free scatter using precomputed ranks
__global__ void k_fill(const int* __restrict__ rows, const int* __restrict__ cols,
                       const float* __restrict__ vals, int E) {
    int e = blockIdx.x * blockDim.x + threadIdx.x;
    if (e >= E) return;
    int r = rows[e];
    int pos = g_start[r] + g_rank[e];
    g_edge[pos] = make_int2(cols[e], __float_as_int(vals[e]));
}

// ---------------- helpers ---------------------------------------------------
__device__ __forceinline__ float ftanh(float x) {
    x = fminf(fmaxf(x, -15.f), 15.f);
    float e = __expf(2.f * x);
    return (e - 1.f) / (e + 1.f);
}
__device__ __forceinline__ float fsoftplus(float x) {
    return log1pf(__expf(x));   // input range ~[-0.46, 1.54]: safe
}

// unpack uint2(half2x2) and fma into fp32 acc
__device__ __forceinline__ void fma_h4(float4& acc, uint2 r, float v) {
    half2 lo = *reinterpret_cast<half2*>(&r.x);
    half2 hi = *reinterpret_cast<half2*>(&r.y);
    float2 f01 = __half22float2(lo);
    float2 f23 = __half22float2(hi);
    acc.x += v * f01.x; acc.y += v * f01.y;
    acc.z += v * f23.x; acc.w += v * f23.y;
}

// 4 lanes per node; lane owns chunk q (8B of fp16). Unroll x8/x4/x1 for MLP.
__device__ __forceinline__ float4 csr_agg4(const uint2* __restrict__ src,
                                           int i, int q) {
    int e   = g_start[i];
    int end = e + g_cnt[i];
    float4 acc = make_float4(0.f, 0.f, 0.f, 0.f);

    for (; e + 8 <= end; e += 8) {
        int2 ed[8];
#pragma unroll
        for (int u = 0; u < 8; ++u) ed[u] = __ldg(&g_edge[e + u]);
        uint2 s[8];
#pragma unroll
        for (int u = 0; u < 8; ++u) s[u] = __ldg(&src[(long)ed[u].x * 4 + q]);
#pragma unroll
        for (int u = 0; u < 8; ++u)
            fma_h4(acc, s[u], __int_as_float(ed[u].y));
    }
    if (e + 4 <= end) {
        int2 ed[4];
#pragma unroll
        for (int u = 0; u < 4; ++u) ed[u] = __ldg(&g_edge[e + u]);
        uint2 s[4];
#pragma unroll
        for (int u = 0; u < 4; ++u) s[u] = __ldg(&src[(long)ed[u].x * 4 + q]);
#pragma unroll
        for (int u = 0; u < 4; ++u)
            fma_h4(acc, s[u], __int_as_float(ed[u].y));
        e += 4;
    }
    for (; e < end; ++e) {
        int2 ed = __ldg(&g_edge[e]);
        uint2 s = __ldg(&src[(long)ed.x * 4 + q]);
        fma_h4(acc, s, __int_as_float(ed.y));
    }
    return acc;
}

// broadcast the 16 h-values of this node's lane-quad into h[16]
__device__ __forceinline__ void group_bcast(float4 acc, float* h, int lane) {
    int base = lane & ~3;
#pragma unroll
    for (int sq = 0; sq < 4; ++sq) {
        h[4 * sq + 0] = __shfl_sync(0xffffffffu, acc.x, base + sq);
        h[4 * sq + 1] = __shfl_sync(0xffffffffu, acc.y, base + sq);
        h[4 * sq + 2] = __shfl_sync(0xffffffffu, acc.z, base + sq);
        h[4 * sq + 3] = __shfl_sync(0xffffffffu, acc.w, base + sq);
    }
}

// ---------------- K_AGG1: Y2 = relu(agg(Y1)) @ W2 (fused) ------------------
__global__ void k_agg1(const float* __restrict__ W2, int N) {
    __shared__ float sW[Hdim * 16];    // W2 padded to 14x16, pads = 0
    for (int t = threadIdx.x; t < Hdim * 16; t += blockDim.x) {
        int k = t >> 4, j = t & 15;
        sW[t] = (j < Hdim) ? W2[k * Hdim + j] : 0.f;
    }
    __syncthreads();

    int tid = blockIdx.x * blockDim.x + threadIdx.x;
    int i = tid >> 2, q = tid & 3;
    bool valid = (i < N);
    int ic = valid ? i : 0;

    float4 acc = make_float4(0.f, 0.f, 0.f, 0.f);
    if (valid) acc = csr_agg4(g_Y1h, ic, q);

    acc.x = fmaxf(acc.x, 0.f); acc.y = fmaxf(acc.y, 0.f);
    acc.z = fmaxf(acc.z, 0.f); acc.w = fmaxf(acc.w, 0.f);

    float h[16];
    group_bcast(acc, h, threadIdx.x & 31);

    int j0 = q * 4;
    float y[4] = {0.f, 0.f, 0.f, 0.f};
#pragma unroll
    for (int k = 0; k < Hdim; ++k) {
        float hk = h[k];
#pragma unroll
        for (int d = 0; d < 4; ++d)
            y[d] += hk * sW[k * 16 + j0 + d];
    }

    if (valid)
        g_Y2h[(long)i * 4 + q] = pack4h(y[0], y[1], y[2], y[3]);
}

// ---------------- K_AGG2: agg(Y2) -> relu -> heads -> out (fused) ----------
__global__ void k_agg2(const float* __restrict__ Wd1, const float* __restrict__ bd1,
                       const float* __restrict__ Wd2, const float* __restrict__ bd2,
                       float* __restrict__ out, int N) {
    __shared__ float sW1[Hdim * 16];   // Wd1 padded 14x16
    __shared__ float sW2[Hdim * 16];   // Wd2 14x16 (natural)
    __shared__ float sB1[16];
    __shared__ float sB2[16];
    for (int t = threadIdx.x; t < Hdim * 16; t += blockDim.x) {
        int k = t >> 4, j = t & 15;
        sW1[t] = (j < Hdim) ? Wd1[k * Hdim + j] : 0.f;
        sW2[t] = Wd2[k * PD + j];
    }
    if (threadIdx.x < 16) {
        sB1[threadIdx.x] = (threadIdx.x < Hdim) ? bd1[threadIdx.x] : 0.f;
        sB2[threadIdx.x] = bd2[threadIdx.x];
    }
    __syncthreads();

    int tid = blockIdx.x * blockDim.x + threadIdx.x;
    int i = tid >> 2, q = tid & 3;
    bool valid = (i < N);
    int ic = valid ? i : 0;

    float4 acc = make_float4(0.f, 0.f, 0.f, 0.f);
    if (valid) acc = csr_agg4(g_Y2h, ic, q);

    acc.x = fmaxf(acc.x, 0.f); acc.y = fmaxf(acc.y, 0.f);
    acc.z = fmaxf(acc.z, 0.f); acc.w = fmaxf(acc.w, 0.f);

    float h[16];
    group_bcast(acc, h, threadIdx.x & 31);

    int j0 = q * 4;
    float pd[4], pp[4];
#pragma unroll
    for (int d = 0; d < 4; ++d) { pd[d] = sB1[j0 + d]; pp[d] = sB2[j0 + d]; }
#pragma unroll
    for (int k = 0; k < Hdim; ++k) {
        float hk = h[k];
#pragma unroll
        for (int d = 0; d < 4; ++d) {
            pd[d] += hk * sW1[k * 16 + j0 + d];
            pp[d] += hk * sW2[k * 16 + j0 + d];
        }
    }

    if (valid) {
        float* o = out + (long)i * OUTC;
#pragma unroll
        for (int d = 0; d < 4; ++d) {
            int j = j0 + d;
            if (j < Hdim) {
                float t = ftanh(pd[d]);
                o[j] = (j < LATC) ? t : fsoftplus(t + SP_INV_1);
            }
            o[Hdim + j] = ftanh(pp[d]);   // 16 perturb outputs: U(14) + m(2)
        }
    }
}

// ---------------- launch ----------------------------------------------------
extern "C" void kernel_launch(void* const* d_in, const int* in_sizes, int n_in,
                              void* d_out, int out_size) {
    const float* X    = (const float*)d_in[0];
    const int*   rows = (const int*)d_in[1];
    const int*   cols = (const int*)d_in[2];
    const float* vals = (const float*)d_in[3];
    const float* W1   = (const float*)d_in[4];
    const float* W2   = (const float*)d_in[5];
    const float* Wd1  = (const float*)d_in[6];
    const float* bd1  = (const float*)d_in[7];
    const float* Wd2  = (const float*)d_in[8];
    const float* bd2  = (const float*)d_in[9];
    float* out = (float*)d_out;

    int N = in_sizes[0] / DIM;
    int E = in_sizes[1];

    const int T = 256;
    int gN  = (N + T - 1) / T;            // node blocks
    int gE  = (E + T - 1) / T;            // edge blocks
    int g4N = (N * 4 + T - 1) / T;        // 4-threads-per-node blocks
    int nb  = (N + 255) / 256;            // scan blocks

    // zero histogram + scan total
    void* cnt_ptr = nullptr;
    cudaGetSymbolAddress(&cnt_ptr, g_cnt);
    cudaMemsetAsync(cnt_ptr, 0, (size_t)(NMAX + 1) * sizeof(int));

    k_fat <<<gN + gE, T>>>(X, W1, rows, N, E, gN);   // gemm1 || histogram+rank
    k_scan<<<nb, 256>>>(N);
    k_fill<<<gE, T>>>(rows, cols, vals, E);
    k_agg1<<<g4N, T>>>(W2, N);
    k_agg2<<<g4N, T>>>(Wd1, bd1, Wd2, bd2, out, N);
}